// round 1
// baseline (speedup 1.0000x reference)
#include <cuda_runtime.h>
#include <math.h>
#include <float.h>

// Problem constants
#define Bn   2
#define Mn   25000
#define Nn   100000
#define Kn   16
#define HIDn 64
#define DIMn 64
#define NGn  8
#define CPGn 8
#define GN_EPS 1e-5f
#define MKn  (Mn * Kn)          // 400000 columns per batch

// ---------------- device scratch (persistent, tiny) ----------------
__device__ double g_s1[Bn][NGn][2];     // stats pass 1: [b][g][sum, sumsq]
__device__ double g_s2[Bn][NGn][2];     // stats pass 2
__device__ __align__(16) float g_w1pe_f[Bn][4][64];    // folded conv1_pe, transposed [c][o]
__device__ __align__(16) float g_b1pe_f[Bn][64];
__device__ __align__(16) float g_w1at_f[Bn][64][64];   // folded conv1_at, transposed [c][o]
__device__ __align__(16) float g_b1at_f[Bn][64];
__device__ __align__(16) float g_w2pe_t[64 * 64];      // pe_w2 transposed [h][o]
__device__ __align__(16) float g_w1at_t[64 * 64];      // at_w1 transposed [c][o] (raw)
__device__ __align__(16) float g_w2at_t[64 * 64];      // at_w2 transposed [h][o]

// ---------------- helpers ----------------
__device__ __forceinline__ void compute_lp(const float* __restrict__ q,
                                           const float* __restrict__ kx,
                                           const int*   __restrict__ idx,
                                           int b, int c, float lp[4]) {
    int m  = c >> 4;
    int id = idx[b * MKn + c];
    float qx = q[(b * 3 + 0) * Mn + m];
    float qy = q[(b * 3 + 1) * Mn + m];
    float qz = q[(b * 3 + 2) * Mn + m];
    float px = kx[(b * 3 + 0) * Nn + id];
    float py = kx[(b * 3 + 1) * Nn + id];
    float pz = kx[(b * 3 + 2) * Nn + id];
    float ox = px - qx, oy = py - qy, oz = pz - qz;
    float d  = sqrtf(ox * ox + oy * oy + oz * oz);
    float r  = 1.0f / fmaxf(d, 1e-12f);
    lp[0] = ox * r; lp[1] = oy * r; lp[2] = oz * r; lp[3] = d;
}

// y[o] = bias[o] + sum_h Wt[h][o] * x[h]   (Wt transposed in shared, 64x64)
__device__ __forceinline__ void gemv64(const float* Wt, const float* bias,
                                       const float* x, float* y) {
#pragma unroll
    for (int o = 0; o < 64; o++) y[o] = bias[o];
#pragma unroll
    for (int h = 0; h < 64; h++) {
        float xv = x[h];
        const float4* w4 = reinterpret_cast<const float4*>(Wt + (h << 6));
#pragma unroll
        for (int j = 0; j < 16; j++) {
            float4 w = w4[j];
            y[4 * j + 0] = fmaf(w.x, xv, y[4 * j + 0]);
            y[4 * j + 1] = fmaf(w.y, xv, y[4 * j + 1]);
            y[4 * j + 2] = fmaf(w.z, xv, y[4 * j + 2]);
            y[4 * j + 3] = fmaf(w.w, xv, y[4 * j + 3]);
        }
    }
}

// ---------------- kernels ----------------
__global__ void k_zero() {
    int t = threadIdx.x;
    if (t < Bn * NGn * 2) {
        ((double*)g_s1)[t] = 0.0;
        ((double*)g_s2)[t] = 0.0;
    }
}

__global__ void k_prep(const float* __restrict__ w2pe,
                       const float* __restrict__ w1at,
                       const float* __restrict__ w2at) {
    int i = blockIdx.x;   // 0..63 (row of original = output channel)
    int j = threadIdx.x;  // 0..63 (col of original = input channel)
    g_w2pe_t[j * 64 + i] = w2pe[i * 64 + j];
    g_w1at_t[j * 64 + i] = w1at[i * 64 + j];
    g_w2at_t[j * 64 + i] = w2at[i * 64 + j];
}

__global__ __launch_bounds__(256) void k_pass1(const float* __restrict__ q,
                                               const float* __restrict__ kx,
                                               const int*   __restrict__ idx,
                                               const float* __restrict__ w1,
                                               const float* __restrict__ b1) {
    __shared__ float sw[4][64];
    __shared__ float sb[64];
    __shared__ float sred[16];
    int t = threadIdx.x, b = blockIdx.y;
    {
        int o = t >> 2, cc = t & 3;
        sw[cc][o] = w1[o * 4 + cc];
    }
    if (t < 64) sb[t] = b1[t];
    if (t < 16) sred[t] = 0.f;
    __syncthreads();

    int c = blockIdx.x * 256 + t;
    bool valid = c < MKn;
    int csafe = valid ? c : 0;
    float lp[4];
    compute_lp(q, kx, idx, b, csafe, lp);

    float gs[8], gq[8];
#pragma unroll
    for (int g = 0; g < 8; g++) { gs[g] = 0.f; gq[g] = 0.f; }
    if (valid) {
#pragma unroll
        for (int o = 0; o < 64; o++) {
            float h = sb[o];
            h = fmaf(sw[0][o], lp[0], h);
            h = fmaf(sw[1][o], lp[1], h);
            h = fmaf(sw[2][o], lp[2], h);
            h = fmaf(sw[3][o], lp[3], h);
            gs[o >> 3] += h;
            gq[o >> 3] = fmaf(h, h, gq[o >> 3]);
        }
    }
#pragma unroll
    for (int g = 0; g < 8; g++) {
        float v1 = gs[g], v2 = gq[g];
        for (int off = 16; off; off >>= 1) {
            v1 += __shfl_down_sync(0xffffffffu, v1, off);
            v2 += __shfl_down_sync(0xffffffffu, v2, off);
        }
        if ((t & 31) == 0) { atomicAdd(&sred[g], v1); atomicAdd(&sred[8 + g], v2); }
    }
    __syncthreads();
    if (t < 16) {
        int g = t & 7, j = t >> 3;  // j=0 sum, j=1 sumsq
        atomicAdd(&g_s1[b][g][j], (double)sred[j * 8 + g]);
    }
}

__global__ void k_fin1(const float* __restrict__ w1, const float* __restrict__ b1,
                       const float* __restrict__ gam, const float* __restrict__ bet) {
    int o = threadIdx.x;  // 64 threads
    double n = (double)CPGn * (double)MKn;
    for (int b = 0; b < Bn; b++) {
        int g = o >> 3;
        double s = g_s1[b][g][0], sq = g_s1[b][g][1];
        double mean = s / n;
        double var  = sq / n - mean * mean;
        float rstd  = (float)(1.0 / sqrt(var + (double)GN_EPS));
        float a  = gam[o] * rstd;
        float cc = bet[o] - (float)mean * a;
        g_b1pe_f[b][o] = fmaf(a, b1[o], cc);
        for (int c = 0; c < 4; c++) g_w1pe_f[b][c][o] = a * w1[o * 4 + c];
    }
}

__global__ __launch_bounds__(256) void k_pass2(const float* __restrict__ q,
                                               const float* __restrict__ kx,
                                               const int*   __restrict__ idx,
                                               const float* __restrict__ b2pe,
                                               const float* __restrict__ b1at) {
    __shared__ __align__(16) float s_w2pe[4096];
    __shared__ __align__(16) float s_w1at[4096];
    __shared__ __align__(16) float s_w1pe[256];
    __shared__ float s_b1pe[64], s_b2pe[64], s_b1at[64];
    __shared__ float sred[16];
    int t = threadIdx.x, b = blockIdx.y;
    for (int i = t; i < 4096; i += 256) {
        s_w2pe[i] = g_w2pe_t[i];
        s_w1at[i] = g_w1at_t[i];
    }
    s_w1pe[t] = ((const float*)g_w1pe_f[b])[t];
    if (t < 64) {
        s_b1pe[t] = g_b1pe_f[b][t];
        s_b2pe[t] = b2pe[t];
        s_b1at[t] = b1at[t];
    }
    if (t < 16) sred[t] = 0.f;
    __syncthreads();

    int c = blockIdx.x * 256 + t;
    bool valid = c < MKn;
    int csafe = valid ? c : 0;
    float lp[4];
    compute_lp(q, kx, idx, b, csafe, lp);

    float u[64];
#pragma unroll
    for (int o = 0; o < 64; o++) {
        float h = s_b1pe[o];
        h = fmaf(s_w1pe[o],       lp[0], h);
        h = fmaf(s_w1pe[64 + o],  lp[1], h);
        h = fmaf(s_w1pe[128 + o], lp[2], h);
        h = fmaf(s_w1pe[192 + o], lp[3], h);
        u[o] = fmaxf(h, 0.f);
    }
    float pe[64];
    gemv64(s_w2pe, s_b2pe, u, pe);
    float h1[64];
    gemv64(s_w1at, s_b1at, pe, h1);

    float gs[8], gq[8];
#pragma unroll
    for (int g = 0; g < 8; g++) { gs[g] = 0.f; gq[g] = 0.f; }
    if (valid) {
#pragma unroll
        for (int o = 0; o < 64; o++) {
            gs[o >> 3] += h1[o];
            gq[o >> 3] = fmaf(h1[o], h1[o], gq[o >> 3]);
        }
    }
#pragma unroll
    for (int g = 0; g < 8; g++) {
        float v1 = gs[g], v2 = gq[g];
        for (int off = 16; off; off >>= 1) {
            v1 += __shfl_down_sync(0xffffffffu, v1, off);
            v2 += __shfl_down_sync(0xffffffffu, v2, off);
        }
        if ((t & 31) == 0) { atomicAdd(&sred[g], v1); atomicAdd(&sred[8 + g], v2); }
    }
    __syncthreads();
    if (t < 16) {
        int g = t & 7, j = t >> 3;
        atomicAdd(&g_s2[b][g][j], (double)sred[j * 8 + g]);
    }
}

__global__ void k_fin2(const float* __restrict__ b1at,
                       const float* __restrict__ gam, const float* __restrict__ bet) {
    int o = threadIdx.x;  // 64 threads
    double n = (double)CPGn * (double)MKn;
    for (int b = 0; b < Bn; b++) {
        int g = o >> 3;
        double s = g_s2[b][g][0], sq = g_s2[b][g][1];
        double mean = s / n;
        double var  = sq / n - mean * mean;
        float rstd  = (float)(1.0 / sqrt(var + (double)GN_EPS));
        float a  = gam[o] * rstd;
        float cc = bet[o] - (float)mean * a;
        g_b1at_f[b][o] = fmaf(a, b1at[o], cc);
        for (int c = 0; c < 64; c++) g_w1at_f[b][c][o] = a * g_w1at_t[c * 64 + o];
    }
}

__global__ __launch_bounds__(256) void k_pass3(const float* __restrict__ q,
                                               const float* __restrict__ kx,
                                               const int*   __restrict__ idx,
                                               const int*   __restrict__ mask,
                                               const float* __restrict__ b2pe,
                                               const float* __restrict__ b2at,
                                               float* __restrict__ out) {
    __shared__ __align__(16) float s_w2pe[4096];
    __shared__ __align__(16) float s_w1at[4096];
    __shared__ __align__(16) float s_w1pe[256];
    __shared__ float s_b1pe[64], s_b2pe[64], s_b1at[64], s_b2at[64];
    int t = threadIdx.x, b = blockIdx.y;
    for (int i = t; i < 4096; i += 256) {
        s_w2pe[i] = g_w2pe_t[i];
        s_w1at[i] = ((const float*)g_w1at_f[b])[i];
    }
    s_w1pe[t] = ((const float*)g_w1pe_f[b])[t];
    if (t < 64) {
        s_b1pe[t] = g_b1pe_f[b][t];
        s_b2pe[t] = b2pe[t];
        s_b1at[t] = g_b1at_f[b][t];
        s_b2at[t] = b2at[t];
    }
    __syncthreads();

    int m = blockIdx.x * 16 + (t >> 4);
    int k = t & 15;
    if (m >= Mn) return;
    int c = m * 16 + k;

    float lp[4];
    compute_lp(q, kx, idx, b, c, lp);

    float u[64];
#pragma unroll
    for (int o = 0; o < 64; o++) {
        float h = s_b1pe[o];
        h = fmaf(s_w1pe[o],       lp[0], h);
        h = fmaf(s_w1pe[64 + o],  lp[1], h);
        h = fmaf(s_w1pe[128 + o], lp[2], h);
        h = fmaf(s_w1pe[192 + o], lp[3], h);
        u[o] = fmaxf(h, 0.f);
    }
    float pe[64];
    gemv64(s_w2pe, s_b2pe, u, pe);
    float v[64];
    gemv64(s_w1at, s_b1at, pe, v);
#pragma unroll
    for (int o = 0; o < 64; o++) v[o] = fmaxf(v[o], 0.f);

    bool mk = mask[b * MKn + c] != 0;

    // attn in chunks of 16 output channels; w2at streamed from global (L1-resident, broadcast)
#pragma unroll
    for (int oc = 0; oc < 4; oc++) {
        float at[16];
#pragma unroll
        for (int j = 0; j < 16; j++) at[j] = s_b2at[oc * 16 + j];
#pragma unroll
        for (int h = 0; h < 64; h++) {
            float vv = v[h];
            const float4* w4 = reinterpret_cast<const float4*>(g_w2at_t + h * 64 + oc * 16);
#pragma unroll
            for (int j = 0; j < 4; j++) {
                float4 w = __ldg(&w4[j]);
                at[4 * j + 0] = fmaf(w.x, vv, at[4 * j + 0]);
                at[4 * j + 1] = fmaf(w.y, vv, at[4 * j + 1]);
                at[4 * j + 2] = fmaf(w.z, vv, at[4 * j + 2]);
                at[4 * j + 3] = fmaf(w.w, vv, at[4 * j + 3]);
            }
        }
#pragma unroll
        for (int j = 0; j < 16; j++) {
            int o = oc * 16 + j;
            float a = mk ? at[j] : -FLT_MAX;
            float mx = a;
#pragma unroll
            for (int off = 1; off < 16; off <<= 1)
                mx = fmaxf(mx, __shfl_xor_sync(0xffffffffu, mx, off));
            float e = __expf(a - mx);
            float s = e;
#pragma unroll
            for (int off = 1; off < 16; off <<= 1)
                s += __shfl_xor_sync(0xffffffffu, s, off);
            float contrib = pe[o] * e * __fdividef(1.f, s);
#pragma unroll
            for (int off = 1; off < 16; off <<= 1)
                contrib += __shfl_xor_sync(0xffffffffu, contrib, off);
            if (k == 0) out[(b * 64 + o) * Mn + m] = contrib;
        }
    }
}

// ---------------- launch ----------------
extern "C" void kernel_launch(void* const* d_in, const int* in_sizes, int n_in,
                              void* d_out, int out_size) {
    const float* q_xyzs  = (const float*)d_in[0];
    const float* k_xyzs  = (const float*)d_in[1];
    const int*   knn_idx = (const int*)d_in[2];
    const int*   mask    = (const int*)d_in[3];
    const float* pe_w1   = (const float*)d_in[4];
    const float* pe_b1   = (const float*)d_in[5];
    const float* pe_g    = (const float*)d_in[6];
    const float* pe_be   = (const float*)d_in[7];
    const float* pe_w2   = (const float*)d_in[8];
    const float* pe_b2   = (const float*)d_in[9];
    const float* at_w1   = (const float*)d_in[10];
    const float* at_b1   = (const float*)d_in[11];
    const float* at_g    = (const float*)d_in[12];
    const float* at_be   = (const float*)d_in[13];
    const float* at_w2   = (const float*)d_in[14];
    const float* at_b2   = (const float*)d_in[15];
    float* out = (float*)d_out;

    k_zero<<<1, 64>>>();
    k_prep<<<64, 64>>>(pe_w2, at_w1, at_w2);

    dim3 gcol((MKn + 255) / 256, Bn);
    k_pass1<<<gcol, 256>>>(q_xyzs, k_xyzs, knn_idx, pe_w1, pe_b1);
    k_fin1<<<1, 64>>>(pe_w1, pe_b1, pe_g, pe_be);
    k_pass2<<<gcol, 256>>>(q_xyzs, k_xyzs, knn_idx, pe_b2, at_b1);
    k_fin2<<<1, 64>>>(at_b1, at_g, at_be);

    dim3 g3((Mn + 15) / 16, Bn);
    k_pass3<<<g3, 256>>>(q_xyzs, k_xyzs, knn_idx, mask, pe_b2, at_b2, out);
}

// round 2
// speedup vs baseline: 2.7532x; 2.7532x over previous
#include <cuda_runtime.h>
#include <math.h>
#include <float.h>

#define Bn   2
#define Mn   25000
#define Nn   100000
#define Kn   16
#define NGn  8
#define CPGn 8
#define GN_EPS 1e-5f
#define MKn  (Mn * Kn)          // 400000 columns per batch

typedef unsigned long long u64;

// ---------------- device scratch ----------------
__device__ double g_s1[Bn][NGn][2];
__device__ double g_s2[Bn][NGn][2];
__device__ __align__(16) float g_w1pe_f[Bn][4][64];    // folded conv1_pe [c][o]
__device__ __align__(16) float g_b1pe_f[Bn][64];
__device__ __align__(16) float g_a2[Bn][64];           // at-GN scale per channel
__device__ __align__(16) float g_c2[Bn][64];           // at-GN shift per channel
__device__ __align__(16) float g_w2pe_t[4096];         // pe_w2 transposed [h][o]
__device__ __align__(16) float g_w1at_t[4096];         // at_w1 transposed [c][o]
__device__ __align__(16) float g_w2at_t[4096];         // at_w2 transposed [h][o]
// big activation scratch (pass2 -> pass3)
__device__ __align__(16) float g_pe_buf[(size_t)Bn * MKn * 64];
__device__ __align__(16) float g_h1_buf[(size_t)Bn * MKn * 64];

// ---------------- f32x2 helpers ----------------
__device__ __forceinline__ u64 fma2(u64 a, u64 b, u64 c) {
    u64 d;
    asm("fma.rn.f32x2 %0, %1, %2, %3;" : "=l"(d) : "l"(a), "l"(b), "l"(c));
    return d;
}
__device__ __forceinline__ u64 add2(u64 a, u64 b) {
    u64 d;
    asm("add.rn.f32x2 %0, %1, %2;" : "=l"(d) : "l"(a), "l"(b));
    return d;
}
__device__ __forceinline__ u64 pack2(float v) {
    u64 r;
    asm("mov.b64 %0, {%1, %1};" : "=l"(r) : "f"(v));
    return r;
}
__device__ __forceinline__ void unpack2(u64 v, float& lo, float& hi) {
    asm("mov.b64 {%0, %1}, %2;" : "=f"(lo), "=f"(hi) : "l"(v));
}

// ---------------- helpers ----------------
__device__ __forceinline__ void compute_lp(const float* __restrict__ q,
                                           const float* __restrict__ kx,
                                           const int*   __restrict__ idx,
                                           int b, int c, float lp[4]) {
    int m  = c >> 4;
    int id = idx[b * MKn + c];
    float qx = q[(b * 3 + 0) * Mn + m];
    float qy = q[(b * 3 + 1) * Mn + m];
    float qz = q[(b * 3 + 2) * Mn + m];
    float px = kx[(b * 3 + 0) * Nn + id];
    float py = kx[(b * 3 + 1) * Nn + id];
    float pz = kx[(b * 3 + 2) * Nn + id];
    float ox = px - qx, oy = py - qy, oz = pz - qz;
    float d  = sqrtf(ox * ox + oy * oy + oz * oz);
    float r  = 1.0f / fmaxf(d, 1e-12f);
    lp[0] = ox * r; lp[1] = oy * r; lp[2] = oz * r; lp[3] = d;
}

// y (32 packed pairs) = bias + Wt^T x,  Wt transposed in shared [h][o], 64x64
__device__ __forceinline__ void gemv64_f2(const float* __restrict__ Wt,
                                          const float* __restrict__ bias,
                                          const float* __restrict__ x,
                                          u64 y[32]) {
    const ulonglong2* b2 = reinterpret_cast<const ulonglong2*>(bias);
#pragma unroll
    for (int j = 0; j < 16; j++) { ulonglong2 bb = b2[j]; y[2*j] = bb.x; y[2*j+1] = bb.y; }
#pragma unroll
    for (int h = 0; h < 64; h++) {
        u64 xx = pack2(x[h]);
        const ulonglong2* w2 = reinterpret_cast<const ulonglong2*>(Wt + (h << 6));
#pragma unroll
        for (int j = 0; j < 16; j++) {
            ulonglong2 w = w2[j];
            y[2*j]   = fma2(w.x, xx, y[2*j]);
            y[2*j+1] = fma2(w.y, xx, y[2*j+1]);
        }
    }
}

// ---------------- kernels ----------------
__global__ void k_prep(const float* __restrict__ w2pe,
                       const float* __restrict__ w1at,
                       const float* __restrict__ w2at) {
    int i = blockIdx.x;   // 0..63 output channel
    int j = threadIdx.x;  // 0..63 input channel
    g_w2pe_t[j * 64 + i] = w2pe[i * 64 + j];
    g_w1at_t[j * 64 + i] = w1at[i * 64 + j];
    g_w2at_t[j * 64 + i] = w2at[i * 64 + j];
    if (i == 0 && j < Bn * NGn * 2) {
        ((double*)g_s1)[j] = 0.0;
        ((double*)g_s2)[j] = 0.0;
    }
}

__global__ __launch_bounds__(256) void k_pass1(const float* __restrict__ q,
                                               const float* __restrict__ kx,
                                               const int*   __restrict__ idx,
                                               const float* __restrict__ w1,
                                               const float* __restrict__ b1) {
    __shared__ float sw[4][64];
    __shared__ float sb[64];
    __shared__ float sred[16];
    int t = threadIdx.x, b = blockIdx.y;
    {
        int o = t >> 2, cc = t & 3;
        sw[cc][o] = w1[o * 4 + cc];
    }
    if (t < 64) sb[t] = b1[t];
    if (t < 16) sred[t] = 0.f;
    __syncthreads();

    int c = blockIdx.x * 256 + t;
    bool valid = c < MKn;
    int csafe = valid ? c : 0;
    float lp[4];
    compute_lp(q, kx, idx, b, csafe, lp);

    float gs[8], gq[8];
#pragma unroll
    for (int g = 0; g < 8; g++) { gs[g] = 0.f; gq[g] = 0.f; }
    if (valid) {
#pragma unroll
        for (int o = 0; o < 64; o++) {
            float h = sb[o];
            h = fmaf(sw[0][o], lp[0], h);
            h = fmaf(sw[1][o], lp[1], h);
            h = fmaf(sw[2][o], lp[2], h);
            h = fmaf(sw[3][o], lp[3], h);
            gs[o >> 3] += h;
            gq[o >> 3] = fmaf(h, h, gq[o >> 3]);
        }
    }
#pragma unroll
    for (int g = 0; g < 8; g++) {
        float v1 = gs[g], v2 = gq[g];
        for (int off = 16; off; off >>= 1) {
            v1 += __shfl_down_sync(0xffffffffu, v1, off);
            v2 += __shfl_down_sync(0xffffffffu, v2, off);
        }
        if ((t & 31) == 0) { atomicAdd(&sred[g], v1); atomicAdd(&sred[8 + g], v2); }
    }
    __syncthreads();
    if (t < 16) {
        int g = t & 7, j = t >> 3;
        atomicAdd(&g_s1[b][g][j], (double)sred[j * 8 + g]);
    }
}

__global__ void k_fin1(const float* __restrict__ w1, const float* __restrict__ b1,
                       const float* __restrict__ gam, const float* __restrict__ bet) {
    int o = threadIdx.x;  // 64 threads
    double n = (double)CPGn * (double)MKn;
    for (int b = 0; b < Bn; b++) {
        int g = o >> 3;
        double s = g_s1[b][g][0], sq = g_s1[b][g][1];
        double mean = s / n;
        double var  = sq / n - mean * mean;
        float rstd  = (float)(1.0 / sqrt(var + (double)GN_EPS));
        float a  = gam[o] * rstd;
        float cc = bet[o] - (float)mean * a;
        g_b1pe_f[b][o] = fmaf(a, b1[o], cc);
        for (int c = 0; c < 4; c++) g_w1pe_f[b][c][o] = a * w1[o * 4 + c];
    }
}

__global__ __launch_bounds__(256) void k_pass2(const float* __restrict__ q,
                                               const float* __restrict__ kx,
                                               const int*   __restrict__ idx,
                                               const float* __restrict__ b2pe,
                                               const float* __restrict__ b1at) {
    __shared__ __align__(16) float s_w2pe[4096];
    __shared__ __align__(16) float s_w1at[4096];
    __shared__ __align__(16) float s_w1pe[256];
    __shared__ __align__(16) float s_b1pe[64];
    __shared__ __align__(16) float s_b2pe[64];
    __shared__ __align__(16) float s_b1at[64];
    __shared__ float sred[16];
    int t = threadIdx.x, b = blockIdx.y;
    for (int i = t; i < 4096; i += 256) {
        s_w2pe[i] = g_w2pe_t[i];
        s_w1at[i] = g_w1at_t[i];
    }
    s_w1pe[t] = ((const float*)g_w1pe_f[b])[t];
    if (t < 64) {
        s_b1pe[t] = g_b1pe_f[b][t];
        s_b2pe[t] = b2pe[t];
        s_b1at[t] = b1at[t];
    }
    if (t < 16) sred[t] = 0.f;
    __syncthreads();

    int c = blockIdx.x * 256 + t;
    bool valid = c < MKn;
    int csafe = valid ? c : 0;
    float lp[4];
    compute_lp(q, kx, idx, b, csafe, lp);

    // u = relu(folded conv1_pe(lp))  -- packed
    float u[64];
    {
        u64 y[32];
        const ulonglong2* b2 = reinterpret_cast<const ulonglong2*>(s_b1pe);
#pragma unroll
        for (int j = 0; j < 16; j++) { ulonglong2 bb = b2[j]; y[2*j] = bb.x; y[2*j+1] = bb.y; }
#pragma unroll
        for (int h = 0; h < 4; h++) {
            u64 xx = pack2(lp[h]);
            const ulonglong2* w2 = reinterpret_cast<const ulonglong2*>(s_w1pe + (h << 6));
#pragma unroll
            for (int j = 0; j < 16; j++) {
                ulonglong2 w = w2[j];
                y[2*j]   = fma2(w.x, xx, y[2*j]);
                y[2*j+1] = fma2(w.y, xx, y[2*j+1]);
            }
        }
#pragma unroll
        for (int i = 0; i < 32; i++) {
            float lo, hi; unpack2(y[i], lo, hi);
            u[2*i] = fmaxf(lo, 0.f); u[2*i+1] = fmaxf(hi, 0.f);
        }
    }

    // pe = conv2_pe(u)
    float pe[64];
    {
        u64 y[32];
        gemv64_f2(s_w2pe, s_b2pe, u, y);
        if (valid) {
            ulonglong2* dst = reinterpret_cast<ulonglong2*>(g_pe_buf + ((size_t)(b * MKn + c) << 6));
#pragma unroll
            for (int j = 0; j < 16; j++) dst[j] = make_ulonglong2(y[2*j], y[2*j+1]);
        }
#pragma unroll
        for (int i = 0; i < 32; i++) unpack2(y[i], pe[2*i], pe[2*i+1]);
    }

    // h1 = conv1_at(pe)  (raw, bias included); store + stats
    {
        u64 y[32];
        gemv64_f2(s_w1at, s_b1at, pe, y);
        if (valid) {
            ulonglong2* dst = reinterpret_cast<ulonglong2*>(g_h1_buf + ((size_t)(b * MKn + c) << 6));
#pragma unroll
            for (int j = 0; j < 16; j++) dst[j] = make_ulonglong2(y[2*j], y[2*j+1]);
        }
        u64 gs2[8], gq2[8];
#pragma unroll
        for (int g = 0; g < 8; g++) { gs2[g] = 0ull; gq2[g] = 0ull; }
        if (valid) {
#pragma unroll
            for (int i = 0; i < 32; i++) {
                int g = i >> 2;
                gs2[g] = add2(gs2[g], y[i]);
                gq2[g] = fma2(y[i], y[i], gq2[g]);
            }
        }
#pragma unroll
        for (int g = 0; g < 8; g++) {
            float l1, h1v, l2, h2v;
            unpack2(gs2[g], l1, h1v);
            unpack2(gq2[g], l2, h2v);
            float v1 = l1 + h1v, v2 = l2 + h2v;
            for (int off = 16; off; off >>= 1) {
                v1 += __shfl_down_sync(0xffffffffu, v1, off);
                v2 += __shfl_down_sync(0xffffffffu, v2, off);
            }
            if ((t & 31) == 0) { atomicAdd(&sred[g], v1); atomicAdd(&sred[8 + g], v2); }
        }
    }
    __syncthreads();
    if (t < 16) {
        int g = t & 7, j = t >> 3;
        atomicAdd(&g_s2[b][g][j], (double)sred[j * 8 + g]);
    }
}

__global__ void k_fin2(const float* __restrict__ gam, const float* __restrict__ bet) {
    int o = threadIdx.x;  // 64 threads
    double n = (double)CPGn * (double)MKn;
    for (int b = 0; b < Bn; b++) {
        int g = o >> 3;
        double s = g_s2[b][g][0], sq = g_s2[b][g][1];
        double mean = s / n;
        double var  = sq / n - mean * mean;
        float rstd  = (float)(1.0 / sqrt(var + (double)GN_EPS));
        float a  = gam[o] * rstd;
        float cc = bet[o] - (float)mean * a;
        g_a2[b][o] = a;
        g_c2[b][o] = cc;
    }
}

__global__ __launch_bounds__(256) void k_pass3(const int* __restrict__ mask,
                                               const float* __restrict__ b2at,
                                               float* __restrict__ out) {
    __shared__ __align__(16) float s_w2at[4096];
    __shared__ __align__(16) float s_a[64];
    __shared__ __align__(16) float s_c[64];
    __shared__ __align__(16) float s_b2at[64];
    int t = threadIdx.x, b = blockIdx.y;
    for (int i = t; i < 4096; i += 256) s_w2at[i] = g_w2at_t[i];
    if (t < 64) {
        s_a[t] = g_a2[b][t];
        s_c[t] = g_c2[b][t];
        s_b2at[t] = b2at[t];
    }
    __syncthreads();

    int m = blockIdx.x * 16 + (t >> 4);
    int k = t & 15;
    if (m >= Mn) return;
    size_t c = (size_t)b * MKn + (size_t)m * 16 + k;
    unsigned smask = (t & 16) ? 0xffff0000u : 0x0000ffffu;

    // v = relu(a * h1 + c)
    float v[64];
    {
        const float4* h4 = reinterpret_cast<const float4*>(g_h1_buf + (c << 6));
        const float4* a4 = reinterpret_cast<const float4*>(s_a);
        const float4* c4 = reinterpret_cast<const float4*>(s_c);
#pragma unroll
        for (int j = 0; j < 16; j++) {
            float4 h = h4[j], aa = a4[j], cc = c4[j];
            v[4*j+0] = fmaxf(fmaf(aa.x, h.x, cc.x), 0.f);
            v[4*j+1] = fmaxf(fmaf(aa.y, h.y, cc.y), 0.f);
            v[4*j+2] = fmaxf(fmaf(aa.z, h.z, cc.z), 0.f);
            v[4*j+3] = fmaxf(fmaf(aa.w, h.w, cc.w), 0.f);
        }
    }
    bool mk = mask[c] != 0;
    const float* peptr = g_pe_buf + (c << 6);

    // attn = conv2_at(v), chunks of 32 output channels; softmax over 16-lane groups
#pragma unroll
    for (int oc = 0; oc < 2; oc++) {
        u64 at2[16];
        {
            const ulonglong2* b2 = reinterpret_cast<const ulonglong2*>(s_b2at + oc * 32);
#pragma unroll
            for (int j = 0; j < 8; j++) { ulonglong2 bb = b2[j]; at2[2*j] = bb.x; at2[2*j+1] = bb.y; }
        }
#pragma unroll
        for (int h = 0; h < 64; h++) {
            u64 xx = pack2(v[h]);
            const ulonglong2* w2 = reinterpret_cast<const ulonglong2*>(s_w2at + (h << 6) + oc * 32);
#pragma unroll
            for (int j = 0; j < 8; j++) {
                ulonglong2 w = w2[j];
                at2[2*j]   = fma2(w.x, xx, at2[2*j]);
                at2[2*j+1] = fma2(w.y, xx, at2[2*j+1]);
            }
        }
        // pe chunk
        float pec[32];
        {
            const float4* p4 = reinterpret_cast<const float4*>(peptr + oc * 32);
#pragma unroll
            for (int j = 0; j < 8; j++) {
                float4 p = p4[j];
                pec[4*j] = p.x; pec[4*j+1] = p.y; pec[4*j+2] = p.z; pec[4*j+3] = p.w;
            }
        }
#pragma unroll
        for (int i = 0; i < 16; i++) {
            float a0, a1; unpack2(at2[i], a0, a1);
#pragma unroll
            for (int half = 0; half < 2; half++) {
                float aval = half ? a1 : a0;
                int lo_o = 2 * i + half;          // within chunk
                int o = oc * 32 + lo_o;
                float a = mk ? aval : -FLT_MAX;
                float mx = a;
#pragma unroll
                for (int off = 8; off; off >>= 1)
                    mx = fmaxf(mx, __shfl_xor_sync(smask, mx, off));
                float e = __expf(a - mx);
                float s = e;
#pragma unroll
                for (int off = 8; off; off >>= 1)
                    s += __shfl_xor_sync(smask, s, off);
                float pc = pec[lo_o] * e;
#pragma unroll
                for (int off = 8; off; off >>= 1)
                    pc += __shfl_xor_sync(smask, pc, off);
                if (k == 0) out[((size_t)b * 64 + o) * Mn + m] = pc * __fdividef(1.f, s);
            }
        }
    }
}

// ---------------- launch ----------------
extern "C" void kernel_launch(void* const* d_in, const int* in_sizes, int n_in,
                              void* d_out, int out_size) {
    const float* q_xyzs  = (const float*)d_in[0];
    const float* k_xyzs  = (const float*)d_in[1];
    const int*   knn_idx = (const int*)d_in[2];
    const int*   mask    = (const int*)d_in[3];
    const float* pe_w1   = (const float*)d_in[4];
    const float* pe_b1   = (const float*)d_in[5];
    const float* pe_g    = (const float*)d_in[6];
    const float* pe_be   = (const float*)d_in[7];
    const float* pe_w2   = (const float*)d_in[8];
    const float* pe_b2   = (const float*)d_in[9];
    const float* at_w1   = (const float*)d_in[10];
    const float* at_b1   = (const float*)d_in[11];
    const float* at_g    = (const float*)d_in[12];
    const float* at_be   = (const float*)d_in[13];
    const float* at_w2   = (const float*)d_in[14];
    const float* at_b2   = (const float*)d_in[15];
    float* out = (float*)d_out;

    k_prep<<<64, 64>>>(pe_w2, at_w1, at_w2);

    dim3 gcol((MKn + 255) / 256, Bn);
    k_pass1<<<gcol, 256>>>(q_xyzs, k_xyzs, knn_idx, pe_w1, pe_b1);
    k_fin1<<<1, 64>>>(pe_w1, pe_b1, pe_g, pe_be);
    k_pass2<<<gcol, 256>>>(q_xyzs, k_xyzs, knn_idx, pe_b2, at_b1);
    k_fin2<<<1, 64>>>(at_g, at_be);

    dim3 g3((Mn + 15) / 16, Bn);
    k_pass3<<<g3, 256>>>(mask, at_b2, out);
}